// round 15
// baseline (speedup 1.0000x reference)
#include <cuda_runtime.h>
#include <cuda_fp16.h>
#include <math.h>
#include <stdint.h>

// ============================================================================
// Problem constants
// ============================================================================
#define NMAX   20000
#define EMAX   320000
#define DMAX   512
#define HMAX   8
#define K1P    52      // layer-1 K padded (50 -> 52)
#define N3P    128     // layer-3 N padded (121 -> 128)

// ============================================================================
// Scratch (static device globals)
// ============================================================================
__device__ int    g_src[EMAX];
__device__ int    g_dst[EMAX];
__device__ int    g_deg[NMAX];
__device__ int    g_off[NMAX + 1];
__device__ int    g_cur[NMAX];
__device__ int    g_csr_src[EMAX];
__device__ __half g_hh  [(size_t)NMAX * DMAX];   // fp16 features (agg input)
__device__ float  g_feat[(size_t)NMAX * DMAX];
__device__ float  g_als [NMAX * 10];   // L1 [0,8N), L2 [8N,9N), L3 [9N,10N)
__device__ float  g_ald [NMAX * 10];
__device__ float  g_xpad [(size_t)NMAX * K1P];
__device__ float  g_w1pad[K1P * 512];            // tf32-rounded
__device__ float  g_w2r  [512 * 512];            // tf32-rounded W2
__device__ float  g_w3pad[512 * N3P];            // tf32-rounded
__device__ float  g_a3s  [N3P];
__device__ float  g_a3d  [N3P];

// ============================================================================
// Helpers
// ============================================================================
__device__ __forceinline__ float lrelu(float x) { return x > 0.f ? x : 0.2f * x; }

__device__ __forceinline__ float tf32_rna(float x) {
    unsigned int r;
    asm("cvt.rna.tf32.f32 %0, %1;" : "=r"(r) : "f"(x));
    return __uint_as_float(r);
}

__device__ __forceinline__ uint32_t smem_u32(const void* p) {
    uint32_t a;
    asm("{ .reg .u64 t; cvta.to.shared.u64 t, %1; cvt.u32.u64 %0, t; }"
        : "=r"(a) : "l"(p));
    return a;
}

// ============================================================================
// Fused setup: deg zero + dot-buffer zero + padding + tf32 pre-rounding of B
// ============================================================================
__global__ void k_setup(const float* __restrict__ x,
                        const float* __restrict__ W1,
                        const float* __restrict__ W2,
                        const float* __restrict__ W3,
                        const float* __restrict__ a3s,
                        const float* __restrict__ a3d, int Nn) {
    int i = blockIdx.x * blockDim.x + threadIdx.x;
    if (i < Nn) g_deg[i] = 0;
    if (i < Nn * 10) { g_als[i] = 0.f; g_ald[i] = 0.f; }
    if (i < Nn * K1P) {
        int r = i / K1P, c = i - r * K1P;
        g_xpad[i] = (c < 50) ? x[r * 50 + c] : 0.f;
    }
    if (i < K1P * 512) {
        int k = i >> 9;
        g_w1pad[i] = (k < 50) ? tf32_rna(W1[i]) : 0.f;
    }
    if (i < 512 * 512)
        g_w2r[i] = tf32_rna(W2[i]);
    if (i < 512 * N3P) {
        int k = i >> 7, n = i & 127;
        g_w3pad[i] = (n < 121) ? tf32_rna(W3[k * 121 + n]) : 0.f;
    }
    if (i < N3P) {
        g_a3s[i] = (i < 121) ? a3s[i] : 0.f;
        g_a3d[i] = (i < 121) ? a3d[i] : 0.f;
    }
}

__global__ void k_convert_hist(const unsigned int* __restrict__ w, int E) {
    bool is64 = true;
    #pragma unroll
    for (int i = 1; i < 64; i += 2) {
        if (w[i] != 0u) { is64 = false; break; }
    }
    int e = blockIdx.x * blockDim.x + threadIdx.x;
    if (e < E) {
        int s, d;
        if (is64) { s = (int)w[2 * e]; d = (int)w[2 * (E + e)]; }
        else      { s = (int)w[e];     d = (int)w[E + e]; }
        g_src[e] = s;
        g_dst[e] = d;
        atomicAdd(&g_deg[d], 1);
    }
}

__global__ void k_scan(int Nn, int E) {
    __shared__ int wsum[32];
    const int T = 1024;
    const int tid  = threadIdx.x;
    const int lane = tid & 31, w = tid >> 5;
    const int CH = (Nn + T - 1) / T;
    int base = tid * CH;
    int lim  = Nn - base;
    if (lim < 0) lim = 0;
    if (lim > CH) lim = CH;

    int sum = 0;
    for (int j = 0; j < lim; j++) sum += g_deg[base + j];

    int v = sum;
    #pragma unroll
    for (int o = 1; o < 32; o <<= 1) {
        int t = __shfl_up_sync(0xffffffffu, v, o);
        if (lane >= o) v += t;
    }
    if (lane == 31) wsum[w] = v;
    __syncthreads();
    if (w == 0) {
        int s = wsum[lane];
        #pragma unroll
        for (int o = 1; o < 32; o <<= 1) {
            int t = __shfl_up_sync(0xffffffffu, s, o);
            if (lane >= o) s += t;
        }
        wsum[lane] = s;
    }
    __syncthreads();
    int run = v - sum + (w > 0 ? wsum[w - 1] : 0);
    for (int j = 0; j < lim; j++) {
        g_off[base + j] = run;
        g_cur[base + j] = run;
        run += g_deg[base + j];
    }
    if (tid == 0) g_off[Nn] = E;
}

__global__ void k_scatter(int E) {
    int e = blockIdx.x * blockDim.x + threadIdx.x;
    if (e < E) {
        int p = atomicAdd(&g_cur[g_dst[e]], 1);
        g_csr_src[p] = g_src[e];
    }
}

// ============================================================================
// 2-term TF32 GEMM, 128x128 block tile, BK=32, 8 warps (warp tile 32x64).
// B pre-rounded to tf32. cp.async 3-stage pipeline (8 iters for K=512).
// fp16 C stores; fp32 attention dots fused in epilogue.
// ============================================================================
#define GBM 128
#define GBN 128
#define GBK 32
#define BKp 36
#define BNp 132
#define ABUF (GBM * BKp * 4)          // 18432
#define BBUF (GBK * BNp * 4)          // 16896
#define BUFB (ABUF + BBUF)            // 35328
#define GSMEM_BYTES (3 * BUFB)        // 105984

__device__ __forceinline__ void mma_tf32(float c[4], const unsigned int a[4],
                                         const unsigned int b[2]) {
    asm volatile(
        "mma.sync.aligned.m16n8k8.row.col.f32.tf32.tf32.f32 "
        "{%0,%1,%2,%3}, {%4,%5,%6,%7}, {%8,%9}, {%0,%1,%2,%3};\n"
        : "+f"(c[0]), "+f"(c[1]), "+f"(c[2]), "+f"(c[3])
        : "r"(a[0]), "r"(a[1]), "r"(a[2]), "r"(a[3]), "r"(b[0]), "r"(b[1]));
}

__device__ __forceinline__ void cp_issue_tile(
    const float* __restrict__ A, const float* __restrict__ B,
    int M, int Ncols, int K, int row0, int col0, int k0,
    int tid, uint32_t smbuf)
{
    // A: thread -> (row = tid>>1, 16 consecutive k at (tid&1)*16)
    const int arow = tid >> 1, akb = (tid & 1) * 16;
    const int grow = row0 + arow;
    const bool rok = grow < M;
    const float* ap = A + (size_t)(rok ? grow : 0) * K + k0 + akb;
    const uint32_t ad = smbuf + (arow * BKp + akb) * 4;
    #pragma unroll
    for (int q = 0; q < 4; q++) {
        int sz = (rok && k0 + akb + q * 4 < K) ? 16 : 0;
        asm volatile("cp.async.cg.shared.global [%0], [%1], 16, %2;"
                     :: "r"(ad + q * 16), "l"(ap + q * 4), "r"(sz));
    }
    // B: thread -> rows {tid>>4, (tid>>4)+16}, 8 consecutive n at (tid&15)*8
    const int bkb = tid >> 4, bn = (tid & 15) * 8;
    const int gn = col0 + bn;
    #pragma unroll
    for (int r = 0; r < 2; r++) {
        int bk = bkb + r * 16;
        int gk = k0 + bk;
        const bool kok = gk < K;
        const float* bp = B + (size_t)(kok ? gk : 0) * Ncols + gn;
        const uint32_t bd = smbuf + ABUF + (bk * BNp + bn) * 4;
        int szb0 = (kok && gn < Ncols) ? 16 : 0;
        int szb1 = (kok && gn + 4 < Ncols) ? 16 : 0;
        asm volatile("cp.async.cg.shared.global [%0], [%1], 16, %2;"
                     :: "r"(bd), "l"(bp), "r"(szb0));
        asm volatile("cp.async.cg.shared.global [%0], [%1], 16, %2;"
                     :: "r"(bd + 16), "l"(bp + 4), "r"(szb1));
    }
}

__global__ __launch_bounds__(256, 2) void k_gemm_tf32(
    const float* __restrict__ A, const float* __restrict__ B,
    __half* __restrict__ C, int M, int N, int K,
    const float* __restrict__ asrc, const float* __restrict__ adst,
    float* __restrict__ als, float* __restrict__ ald,
    int H, int Chead)
{
    extern __shared__ char sm[];
    const uint32_t smb = smem_u32(sm);

    const int tid  = threadIdx.x;
    const int lane = tid & 31, warp = tid >> 5;
    const int wm = warp >> 1, wn = warp & 1;
    const int g = lane >> 2, tq = lane & 3;
    const int row0 = blockIdx.y * GBM;
    const int col0 = blockIdx.x * GBN;

    float c[2][8][4];
    #pragma unroll
    for (int i = 0; i < 2; i++)
        #pragma unroll
        for (int j = 0; j < 8; j++)
            #pragma unroll
            for (int q = 0; q < 4; q++) c[i][j][q] = 0.f;

    const int nIt = (K + GBK - 1) / GBK;

    cp_issue_tile(A, B, M, N, K, row0, col0, 0, tid, smb);
    asm volatile("cp.async.commit_group;" ::: "memory");
    if (nIt > 1) {
        cp_issue_tile(A, B, M, N, K, row0, col0, GBK, tid, smb + BUFB);
        asm volatile("cp.async.commit_group;" ::: "memory");
    }

    for (int it = 0; it < nIt; it++) {
        if (it < nIt - 1)
            asm volatile("cp.async.wait_group 1;" ::: "memory");
        else
            asm volatile("cp.async.wait_group 0;" ::: "memory");
        __syncthreads();

        if (it + 2 < nIt) {
            cp_issue_tile(A, B, M, N, K, row0, col0, (it + 2) * GBK, tid,
                          smb + ((it + 2) % 3) * BUFB);
            asm volatile("cp.async.commit_group;" ::: "memory");
        }

        const float* as_ = (const float*)(sm + (it % 3) * BUFB);
        const float* bs_ = (const float*)(sm + (it % 3) * BUFB + ABUF);

        #pragma unroll
        for (int ks = 0; ks < 4; ks++) {
            const int kb = ks * 8;
            float arf[2][4];
            #pragma unroll
            for (int tm = 0; tm < 2; tm++) {
                int m = wm * 32 + tm * 16 + g;
                const float* r0 = as_ + m * BKp;
                const float* r1 = as_ + (m + 8) * BKp;
                arf[tm][0] = r0[kb + tq];
                arf[tm][1] = r1[kb + tq];
                arf[tm][2] = r0[kb + tq + 4];
                arf[tm][3] = r1[kb + tq + 4];
            }
            unsigned int bfh[8][2];
            #pragma unroll
            for (int tn = 0; tn < 8; tn++) {
                int n = wn * 64 + tn * 8 + g;
                bfh[tn][0] = __float_as_uint(bs_[(kb + tq) * BNp + n]);
                bfh[tn][1] = __float_as_uint(bs_[(kb + tq + 4) * BNp + n]);
            }
            unsigned int afh[2][4], afl[2][4];
            #pragma unroll
            for (int tm = 0; tm < 2; tm++)
                #pragma unroll
                for (int q = 0; q < 4; q++) {
                    float h = tf32_rna(arf[tm][q]);
                    float l = tf32_rna(arf[tm][q] - h);
                    afh[tm][q] = __float_as_uint(h);
                    afl[tm][q] = __float_as_uint(l);
                }
            #pragma unroll
            for (int tm = 0; tm < 2; tm++)
                #pragma unroll
                for (int tn = 0; tn < 8; tn++) {
                    mma_tf32(c[tm][tn], afh[tm], bfh[tn]);
                    mma_tf32(c[tm][tn], afl[tm], bfh[tn]);
                }
        }
    }

    // ---- epilogue: fp32 attention dots + fp16 C stores ----
    const int hh = (col0 + wn * 64) / Chead;
    #pragma unroll
    for (int tm = 0; tm < 2; tm++) {
        float l0s = 0.f, l0d = 0.f, l1s = 0.f, l1d = 0.f;
        #pragma unroll
        for (int tn = 0; tn < 8; tn++) {
            int gm0 = row0 + wm * 32 + tm * 16 + g;
            int gn0 = col0 + wn * 64 + tn * 8 + 2 * tq;
            float as0 = asrc[gn0], ad0 = adst[gn0];
            float as1 = asrc[gn0 + 1], ad1 = adst[gn0 + 1];

            l0s = fmaf(c[tm][tn][0], as0, fmaf(c[tm][tn][1], as1, l0s));
            l0d = fmaf(c[tm][tn][0], ad0, fmaf(c[tm][tn][1], ad1, l0d));
            l1s = fmaf(c[tm][tn][2], as0, fmaf(c[tm][tn][3], as1, l1s));
            l1d = fmaf(c[tm][tn][2], ad0, fmaf(c[tm][tn][3], ad1, l1d));

            if (gm0 < M)
                *(__half2*)&C[(size_t)gm0 * N + gn0] =
                    __floats2half2_rn(c[tm][tn][0], c[tm][tn][1]);
            if (gm0 + 8 < M)
                *(__half2*)&C[(size_t)(gm0 + 8) * N + gn0] =
                    __floats2half2_rn(c[tm][tn][2], c[tm][tn][3]);
        }
        #pragma unroll
        for (int o = 1; o <= 2; o <<= 1) {
            l0s += __shfl_xor_sync(0xffffffffu, l0s, o);
            l0d += __shfl_xor_sync(0xffffffffu, l0d, o);
            l1s += __shfl_xor_sync(0xffffffffu, l1s, o);
            l1d += __shfl_xor_sync(0xffffffffu, l1d, o);
        }
        if (tq == 0) {
            int r0 = row0 + wm * 32 + tm * 16 + g;
            if (r0 < M) {
                atomicAdd(&als[r0 * H + hh], l0s);
                atomicAdd(&ald[r0 * H + hh], l0d);
            }
            if (r0 + 8 < M) {
                atomicAdd(&als[(r0 + 8) * H + hh], l1s);
                atomicAdd(&ald[(r0 + 8) * H + hh], l1d);
            }
        }
    }
}

// ============================================================================
// FUSED softmax + aggregation: one block (128 thr) per destination node.
// ============================================================================
__device__ __forceinline__ void acc4_h(float4& acc, float a, uint2 raw) {
    __half2 p01 = *(__half2*)&raw.x;
    __half2 p23 = *(__half2*)&raw.y;
    float2 f01 = __half22float2(p01);
    float2 f23 = __half22float2(p23);
    acc.x = fmaf(a, f01.x, acc.x); acc.y = fmaf(a, f01.y, acc.y);
    acc.z = fmaf(a, f23.x, acc.z); acc.w = fmaf(a, f23.y, acc.w);
}

template <int H, int C, int CAP, int VEC, bool ELU>
__global__ void k_fused_agg(const __half* __restrict__ h,
                            const float* __restrict__ als,
                            const float* __restrict__ ald,
                            const float* __restrict__ bias,
                            float* __restrict__ outp, int Dout)
{
    constexpr int DS = H * C;
    constexpr int BT = 128;
    __shared__ int   ssrc[CAP];
    __shared__ float salpha[CAP * H];
    __shared__ float red[BT];
    __shared__ float sals[H], sald[H], s_m[H], sexs[H], srz[H];

    const int t   = blockIdx.x;
    const int tid = threadIdx.x;
    const int beg = g_off[t], end = g_off[t + 1];
    const int deg = end - beg;
    const bool cached = (deg <= CAP);

    if (tid < H) {
        sals[tid] = als[t * H + tid];
        sald[tid] = ald[t * H + tid];
    }
    __syncthreads();

    const int hh_t = (H == 8) ? (tid & 7) : 0;
    const float myald = sald[hh_t];
    float ma = sals[hh_t];

    for (int base = 0; base < deg; base += CAP) {
        int n = min(CAP, deg - base);
        for (int i = tid; i < n; i += BT) ssrc[i] = g_csr_src[beg + base + i];
        __syncthreads();
        if (H == 8) {
            for (int j = tid; j < n * 8; j += BT) {
                float v = als[ssrc[j >> 3] * 8 + (j & 7)];
                salpha[j] = v;
                ma = fmaxf(ma, v);
            }
        } else {
            for (int i = tid; i < n; i += BT) {
                float v = als[ssrc[i]];
                salpha[i] = v;
                ma = fmaxf(ma, v);
            }
        }
        __syncthreads();
    }

    if (H == 8) {
        red[(tid & 7) * 16 + (tid >> 3)] = ma;
        __syncthreads();
        if (tid < 8) {
            float m = red[tid * 16];
            #pragma unroll
            for (int i = 1; i < 16; i++) m = fmaxf(m, red[tid * 16 + i]);
            m = lrelu(m + sald[tid]);
            s_m[tid]  = m;
            sexs[tid] = expf(lrelu(sals[tid] + sald[tid]) - m);
        }
    } else {
        #pragma unroll
        for (int o = 16; o > 0; o >>= 1)
            ma = fmaxf(ma, __shfl_xor_sync(0xffffffffu, ma, o));
        if ((tid & 31) == 0) red[tid >> 5] = ma;
        __syncthreads();
        if (tid == 0) {
            float m = fmaxf(fmaxf(red[0], red[1]), fmaxf(red[2], red[3]));
            m = lrelu(m + sald[0]);
            s_m[0]  = m;
            sexs[0] = expf(lrelu(sals[0] + sald[0]) - m);
        }
    }
    __syncthreads();
    const float mym = s_m[hh_t];

    float4 acc = make_float4(0.f, 0.f, 0.f, 0.f);
    float  acc1 = 0.f;
    int c4 = 0, hh_ch = 0;
    if (VEC == 4) {
        c4 = tid * 4;
        hh_ch = c4 / C;
        acc4_h(acc, sexs[hh_ch], *(const uint2*)&h[(size_t)t * DS + c4]);
    } else {
        acc1 = sexs[0] * __half2float(h[(size_t)t * DS + tid]);
    }

    float zloc = 0.f;
    for (int base = 0; base < deg; base += CAP) {
        int n = min(CAP, deg - base);
        if (!cached) {
            for (int i = tid; i < n; i += BT) ssrc[i] = g_csr_src[beg + base + i];
            __syncthreads();
            if (H == 8) {
                for (int j = tid; j < n * 8; j += BT) {
                    float v = als[ssrc[j >> 3] * 8 + (j & 7)];
                    float a = expf(lrelu(v + myald) - mym);
                    salpha[j] = a;
                    zloc += a;
                }
            } else {
                for (int i = tid; i < n; i += BT) {
                    float a = expf(lrelu(als[ssrc[i]] + myald) - mym);
                    salpha[i] = a;
                    zloc += a;
                }
            }
        } else {
            if (H == 8) {
                for (int j = tid; j < n * 8; j += BT) {
                    float a = expf(lrelu(salpha[j] + myald) - mym);
                    salpha[j] = a;
                    zloc += a;
                }
            } else {
                for (int i = tid; i < n; i += BT) {
                    float a = expf(lrelu(salpha[i] + myald) - mym);
                    salpha[i] = a;
                    zloc += a;
                }
            }
        }
        __syncthreads();

        if (VEC == 4) {
            int p = 0;
            for (; p + 3 < n; p += 4) {
                int s0 = ssrc[p],     s1 = ssrc[p + 1];
                int s2 = ssrc[p + 2], s3 = ssrc[p + 3];
                float a0 = salpha[(H == 8) ? (p * 8 + hh_ch)       : p];
                float a1 = salpha[(H == 8) ? ((p + 1) * 8 + hh_ch) : (p + 1)];
                float a2 = salpha[(H == 8) ? ((p + 2) * 8 + hh_ch) : (p + 2)];
                float a3 = salpha[(H == 8) ? ((p + 3) * 8 + hh_ch) : (p + 3)];
                uint2 r0 = *(const uint2*)&h[(size_t)s0 * DS + c4];
                uint2 r1 = *(const uint2*)&h[(size_t)s1 * DS + c4];
                uint2 r2 = *(const uint2*)&h[(size_t)s2 * DS + c4];
                uint2 r3 = *(const uint2*)&h[(size_t)s3 * DS + c4];
                acc4_h(acc, a0, r0);
                acc4_h(acc, a1, r1);
                acc4_h(acc, a2, r2);
                acc4_h(acc, a3, r3);
            }
            for (; p < n; p++) {
                int s0 = ssrc[p];
                float a0 = salpha[(H == 8) ? (p * 8 + hh_ch) : p];
                acc4_h(acc, a0, *(const uint2*)&h[(size_t)s0 * DS + c4]);
            }
        } else {
            int p = 0;
            for (; p + 3 < n; p += 4) {
                int s0 = ssrc[p],     s1 = ssrc[p + 1];
                int s2 = ssrc[p + 2], s3 = ssrc[p + 3];
                float a0 = salpha[p], a1 = salpha[p + 1];
                float a2 = salpha[p + 2], a3 = salpha[p + 3];
                float v0 = __half2float(h[(size_t)s0 * DS + tid]);
                float v1 = __half2float(h[(size_t)s1 * DS + tid]);
                float v2 = __half2float(h[(size_t)s2 * DS + tid]);
                float v3 = __half2float(h[(size_t)s3 * DS + tid]);
                acc1 = fmaf(a0, v0, acc1);
                acc1 = fmaf(a1, v1, acc1);
                acc1 = fmaf(a2, v2, acc1);
                acc1 = fmaf(a3, v3, acc1);
            }
            for (; p < n; p++)
                acc1 = fmaf(salpha[p],
                            __half2float(h[(size_t)ssrc[p] * DS + tid]), acc1);
        }
        __syncthreads();
    }

    if (H == 8) {
        red[(tid & 7) * 16 + (tid >> 3)] = zloc;
        __syncthreads();
        if (tid < 8) {
            float z = 0.f;
            #pragma unroll
            for (int i = 0; i < 16; i++) z += red[tid * 16 + i];
            srz[tid] = 1.f / (z + sexs[tid] + 1e-16f);
        }
    } else {
        #pragma unroll
        for (int o = 16; o > 0; o >>= 1)
            zloc += __shfl_xor_sync(0xffffffffu, zloc, o);
        if ((tid & 31) == 0) red[tid >> 5] = zloc;
        __syncthreads();
        if (tid == 0) {
            float z = red[0] + red[1] + red[2] + red[3];
            srz[0] = 1.f / (z + sexs[0] + 1e-16f);
        }
    }
    __syncthreads();

    if (VEC == 4) {
        float rz = srz[hh_ch];
        float4 b = *(const float4*)&bias[c4];
        acc.x = fmaf(acc.x, rz, b.x);
        acc.y = fmaf(acc.y, rz, b.y);
        acc.z = fmaf(acc.z, rz, b.z);
        acc.w = fmaf(acc.w, rz, b.w);
        if (ELU) {
            acc.x = acc.x > 0.f ? acc.x : expf(acc.x) - 1.f;
            acc.y = acc.y > 0.f ? acc.y : expf(acc.y) - 1.f;
            acc.z = acc.z > 0.f ? acc.z : expf(acc.z) - 1.f;
            acc.w = acc.w > 0.f ? acc.w : expf(acc.w) - 1.f;
        }
        *(float4*)&outp[(size_t)t * Dout + c4] = acc;
    } else {
        if (tid < Dout) {
            float v = fmaf(acc1, srz[0], bias[tid]);
            if (ELU) v = v > 0.f ? v : expf(v) - 1.f;
            outp[(size_t)t * Dout + tid] = v;
        }
    }
}

// ============================================================================
// Host launch
// ============================================================================
static inline int cdiv(int a, int b) { return (a + b - 1) / b; }

extern "C" void kernel_launch(void* const* d_in, const int* in_sizes, int n_in,
                              void* d_out, int out_size) {
    const float* x   = (const float*)d_in[0];
    const void*  ei  = d_in[1];
    const float* W1  = (const float*)d_in[2];
    const float* a1s = (const float*)d_in[3];
    const float* a1d = (const float*)d_in[4];
    const float* b1  = (const float*)d_in[5];
    const float* W2  = (const float*)d_in[6];
    const float* a2s = (const float*)d_in[7];
    const float* a2d = (const float*)d_in[8];
    const float* b2  = (const float*)d_in[9];
    const float* W3  = (const float*)d_in[10];
    const float* a3s = (const float*)d_in[11];
    const float* a3d = (const float*)d_in[12];
    const float* b3  = (const float*)d_in[13];
    float* out = (float*)d_out;

    const int Nn = in_sizes[0] / 50;   // 20000
    const int E  = in_sizes[1] / 2;    // 320000

    __half* h;
    float *feat, *xpad, *w1pad, *w2r, *w3pad, *a3sp, *a3dp, *als, *ald;
    cudaGetSymbolAddress((void**)&h,     g_hh);
    cudaGetSymbolAddress((void**)&feat,  g_feat);
    cudaGetSymbolAddress((void**)&xpad,  g_xpad);
    cudaGetSymbolAddress((void**)&w1pad, g_w1pad);
    cudaGetSymbolAddress((void**)&w2r,   g_w2r);
    cudaGetSymbolAddress((void**)&w3pad, g_w3pad);
    cudaGetSymbolAddress((void**)&a3sp,  g_a3s);
    cudaGetSymbolAddress((void**)&a3dp,  g_a3d);
    cudaGetSymbolAddress((void**)&als,   g_als);
    cudaGetSymbolAddress((void**)&ald,   g_ald);

    float* als2 = als + (size_t)Nn * 8;
    float* ald2 = ald + (size_t)Nn * 8;
    float* als3 = als + (size_t)Nn * 9;
    float* ald3 = ald + (size_t)Nn * 9;

    cudaFuncSetAttribute(k_gemm_tf32,
                         cudaFuncAttributeMaxDynamicSharedMemorySize, GSMEM_BYTES);

    // ---- fused setup + graph preprocessing ----
    k_setup       <<<cdiv(Nn * K1P, 256), 256>>>(x, W1, W2, W3, a3s, a3d, Nn);
    k_convert_hist<<<cdiv(E, 256), 256>>>((const unsigned int*)ei, E);
    k_scan        <<<1, 1024>>>(Nn, E);
    k_scatter     <<<cdiv(E, 256), 256>>>(E);

    // ---------------- Layer 1: 50 -> 8 heads x 64, concat ----------------
    {
        dim3 grid(cdiv(512, GBN), cdiv(Nn, GBM));
        k_gemm_tf32<<<grid, 256, GSMEM_BYTES>>>(xpad, w1pad, h, Nn, 512, K1P,
                                                a1s, a1d, als, ald, 8, 64);
        k_fused_agg<8, 64, 256, 4, true><<<Nn, 128>>>(h, als, ald, b1, feat, 512);
    }

    // ---------------- Layer 2: 512 -> 512, 1 head ----------------
    {
        dim3 grid(cdiv(512, GBN), cdiv(Nn, GBM));
        k_gemm_tf32<<<grid, 256, GSMEM_BYTES>>>(feat, w2r, h, Nn, 512, 512,
                                                a2s, a2d, als2, ald2, 1, 512);
        k_fused_agg<1, 512, 1024, 4, true><<<Nn, 128>>>(h, als2, ald2, b2, feat, 512);
    }

    // ---------------- Layer 3: 512 -> 121 (padded to 128), mean=identity --
    {
        dim3 grid(cdiv(N3P, GBN), cdiv(Nn, GBM));
        k_gemm_tf32<<<grid, 256, GSMEM_BYTES>>>(feat, w3pad, h, Nn, N3P, 512,
                                                a3sp, a3dp, als3, ald3, 1, N3P);
        k_fused_agg<1, 128, 1024, 1, false><<<Nn, 128>>>(h, als3, ald3, b3, out, 121);
    }
}

// round 16
// speedup vs baseline: 1.0672x; 1.0672x over previous
#include <cuda_runtime.h>
#include <cuda_fp16.h>
#include <math.h>
#include <stdint.h>

// ============================================================================
// Problem constants
// ============================================================================
#define NMAX   20000
#define EMAX   320000
#define DMAX   512
#define HMAX   8
#define K1P    52      // layer-1 K padded (50 -> 52)
#define N3P    128     // layer-3 N padded (121 -> 128)

// ============================================================================
// Scratch (static device globals)
// ============================================================================
__device__ int    g_src[EMAX];
__device__ int    g_dst[EMAX];
__device__ int    g_deg[NMAX];
__device__ int    g_off[NMAX + 1];
__device__ int    g_cur[NMAX];
__device__ int    g_csr_src[EMAX];
__device__ __half g_hh  [(size_t)NMAX * DMAX];   // fp16 features (agg input)
__device__ float  g_feat[(size_t)NMAX * DMAX];
__device__ float  g_als [NMAX * 10];   // L1 [0,8N), L2 [8N,9N), L3 [9N,10N)
__device__ float  g_ald [NMAX * 10];
__device__ float  g_xpad [(size_t)NMAX * K1P];
__device__ float  g_w1pad[K1P * 512];            // tf32-rounded
__device__ float  g_w2r  [512 * 512];            // tf32-rounded W2
__device__ float  g_w3pad[512 * N3P];            // tf32-rounded
__device__ float  g_a3s  [N3P];
__device__ float  g_a3d  [N3P];

// ============================================================================
// Helpers
// ============================================================================
__device__ __forceinline__ float lrelu(float x) { return x > 0.f ? x : 0.2f * x; }

__device__ __forceinline__ float tf32_rna(float x) {
    unsigned int r;
    asm("cvt.rna.tf32.f32 %0, %1;" : "=r"(r) : "f"(x));
    return __uint_as_float(r);
}

__device__ __forceinline__ uint32_t smem_u32(const void* p) {
    uint32_t a;
    asm("{ .reg .u64 t; cvta.to.shared.u64 t, %1; cvt.u32.u64 %0, t; }"
        : "=r"(a) : "l"(p));
    return a;
}

// ============================================================================
// Setup: dot-buffer zero + padding + tf32 pre-rounding of B (legacy stream)
// ============================================================================
__global__ void k_setup(const float* __restrict__ x,
                        const float* __restrict__ W1,
                        const float* __restrict__ W2,
                        const float* __restrict__ W3,
                        const float* __restrict__ a3s,
                        const float* __restrict__ a3d, int Nn) {
    int i = blockIdx.x * blockDim.x + threadIdx.x;
    if (i < Nn * 10) { g_als[i] = 0.f; g_ald[i] = 0.f; }
    if (i < Nn * K1P) {
        int r = i / K1P, c = i - r * K1P;
        g_xpad[i] = (c < 50) ? x[r * 50 + c] : 0.f;
    }
    if (i < K1P * 512) {
        int k = i >> 9;
        g_w1pad[i] = (k < 50) ? tf32_rna(W1[i]) : 0.f;
    }
    if (i < 512 * 512)
        g_w2r[i] = tf32_rna(W2[i]);
    if (i < 512 * N3P) {
        int k = i >> 7, n = i & 127;
        g_w3pad[i] = (n < 121) ? tf32_rna(W3[k * 121 + n]) : 0.f;
    }
    if (i < N3P) {
        g_a3s[i] = (i < 121) ? a3s[i] : 0.f;
        g_a3d[i] = (i < 121) ? a3d[i] : 0.f;
    }
}

// ---- CSR chain (side stream) ----
__global__ void k_zero_deg(int Nn) {
    int i = blockIdx.x * blockDim.x + threadIdx.x;
    if (i < Nn) g_deg[i] = 0;
}

__global__ void k_convert_hist(const unsigned int* __restrict__ w, int E) {
    bool is64 = true;
    #pragma unroll
    for (int i = 1; i < 64; i += 2) {
        if (w[i] != 0u) { is64 = false; break; }
    }
    int e = blockIdx.x * blockDim.x + threadIdx.x;
    if (e < E) {
        int s, d;
        if (is64) { s = (int)w[2 * e]; d = (int)w[2 * (E + e)]; }
        else      { s = (int)w[e];     d = (int)w[E + e]; }
        g_src[e] = s;
        g_dst[e] = d;
        atomicAdd(&g_deg[d], 1);
    }
}

__global__ void k_scan(int Nn, int E) {
    __shared__ int wsum[32];
    const int T = 1024;
    const int tid  = threadIdx.x;
    const int lane = tid & 31, w = tid >> 5;
    const int CH = (Nn + T - 1) / T;
    int base = tid * CH;
    int lim  = Nn - base;
    if (lim < 0) lim = 0;
    if (lim > CH) lim = CH;

    int sum = 0;
    for (int j = 0; j < lim; j++) sum += g_deg[base + j];

    int v = sum;
    #pragma unroll
    for (int o = 1; o < 32; o <<= 1) {
        int t = __shfl_up_sync(0xffffffffu, v, o);
        if (lane >= o) v += t;
    }
    if (lane == 31) wsum[w] = v;
    __syncthreads();
    if (w == 0) {
        int s = wsum[lane];
        #pragma unroll
        for (int o = 1; o < 32; o <<= 1) {
            int t = __shfl_up_sync(0xffffffffu, s, o);
            if (lane >= o) s += t;
        }
        wsum[lane] = s;
    }
    __syncthreads();
    int run = v - sum + (w > 0 ? wsum[w - 1] : 0);
    for (int j = 0; j < lim; j++) {
        g_off[base + j] = run;
        g_cur[base + j] = run;
        run += g_deg[base + j];
    }
    if (tid == 0) g_off[Nn] = E;
}

__global__ void k_scatter(int E) {
    int e = blockIdx.x * blockDim.x + threadIdx.x;
    if (e < E) {
        int p = atomicAdd(&g_cur[g_dst[e]], 1);
        g_csr_src[p] = g_src[e];
    }
}

// ============================================================================
// 2-term TF32 GEMM, 128x128 block tile, BK=16, 8 warps (warp tile 32x64).
// B pre-rounded to tf32. cp.async 3-stage pipeline. fp16 C stores;
// fp32 attention dots fused in epilogue. (Proven R14 configuration.)
// ============================================================================
#define GBM 128
#define GBN 128
#define GBK 16
#define BKp 20
#define BNp 132
#define ABUF (GBM * BKp * 4)
#define BBUF (GBK * BNp * 4)
#define BUFB (ABUF + BBUF)
#define GSMEM_BYTES (3 * BUFB)

__device__ __forceinline__ void mma_tf32(float c[4], const unsigned int a[4],
                                         const unsigned int b[2]) {
    asm volatile(
        "mma.sync.aligned.m16n8k8.row.col.f32.tf32.tf32.f32 "
        "{%0,%1,%2,%3}, {%4,%5,%6,%7}, {%8,%9}, {%0,%1,%2,%3};\n"
        : "+f"(c[0]), "+f"(c[1]), "+f"(c[2]), "+f"(c[3])
        : "r"(a[0]), "r"(a[1]), "r"(a[2]), "r"(a[3]), "r"(b[0]), "r"(b[1]));
}

__device__ __forceinline__ void cp_issue_tile(
    const float* __restrict__ A, const float* __restrict__ B,
    int M, int Ncols, int K, int row0, int col0, int k0,
    int tid, uint32_t smbuf)
{
    const int arow = tid >> 1, akb = (tid & 1) * 8;
    const int grow = row0 + arow;
    const bool rok = grow < M;
    const float* ap = A + (size_t)(rok ? grow : 0) * K + k0 + akb;
    const uint32_t ad = smbuf + (arow * BKp + akb) * 4;
    int sza0 = (rok && k0 + akb < K) ? 16 : 0;
    int sza1 = (rok && k0 + akb + 4 < K) ? 16 : 0;
    asm volatile("cp.async.cg.shared.global [%0], [%1], 16, %2;"
                 :: "r"(ad), "l"(ap), "r"(sza0));
    asm volatile("cp.async.cg.shared.global [%0], [%1], 16, %2;"
                 :: "r"(ad + 16), "l"(ap + 4), "r"(sza1));
    const int bk = tid >> 4, bn = (tid & 15) * 8;
    const int gk = k0 + bk, gn = col0 + bn;
    const bool kok = gk < K;
    const float* bp = B + (size_t)(kok ? gk : 0) * Ncols + gn;
    const uint32_t bd = smbuf + ABUF + (bk * BNp + bn) * 4;
    int szb0 = (kok && gn < Ncols) ? 16 : 0;
    int szb1 = (kok && gn + 4 < Ncols) ? 16 : 0;
    asm volatile("cp.async.cg.shared.global [%0], [%1], 16, %2;"
                 :: "r"(bd), "l"(bp), "r"(szb0));
    asm volatile("cp.async.cg.shared.global [%0], [%1], 16, %2;"
                 :: "r"(bd + 16), "l"(bp + 4), "r"(szb1));
}

__global__ __launch_bounds__(256, 2) void k_gemm_tf32(
    const float* __restrict__ A, const float* __restrict__ B,
    __half* __restrict__ C, int M, int N, int K,
    const float* __restrict__ asrc, const float* __restrict__ adst,
    float* __restrict__ als, float* __restrict__ ald,
    int H, int Chead)
{
    extern __shared__ char sm[];
    const uint32_t smb = smem_u32(sm);

    const int tid  = threadIdx.x;
    const int lane = tid & 31, warp = tid >> 5;
    const int wm = warp >> 1, wn = warp & 1;
    const int g = lane >> 2, tq = lane & 3;
    const int row0 = blockIdx.y * GBM;
    const int col0 = blockIdx.x * GBN;

    float c[2][8][4];
    #pragma unroll
    for (int i = 0; i < 2; i++)
        #pragma unroll
        for (int j = 0; j < 8; j++)
            #pragma unroll
            for (int q = 0; q < 4; q++) c[i][j][q] = 0.f;

    const int nIt = (K + GBK - 1) / GBK;

    cp_issue_tile(A, B, M, N, K, row0, col0, 0, tid, smb);
    asm volatile("cp.async.commit_group;" ::: "memory");
    if (nIt > 1) {
        cp_issue_tile(A, B, M, N, K, row0, col0, GBK, tid, smb + BUFB);
        asm volatile("cp.async.commit_group;" ::: "memory");
    }

    for (int it = 0; it < nIt; it++) {
        if (it < nIt - 1)
            asm volatile("cp.async.wait_group 1;" ::: "memory");
        else
            asm volatile("cp.async.wait_group 0;" ::: "memory");
        __syncthreads();

        if (it + 2 < nIt) {
            cp_issue_tile(A, B, M, N, K, row0, col0, (it + 2) * GBK, tid,
                          smb + ((it + 2) % 3) * BUFB);
            asm volatile("cp.async.commit_group;" ::: "memory");
        }

        const float* as_ = (const float*)(sm + (it % 3) * BUFB);
        const float* bs_ = (const float*)(sm + (it % 3) * BUFB + ABUF);

        #pragma unroll
        for (int ks = 0; ks < 2; ks++) {
            const int kb = ks * 8;
            float arf[2][4];
            #pragma unroll
            for (int tm = 0; tm < 2; tm++) {
                int m = wm * 32 + tm * 16 + g;
                const float* r0 = as_ + m * BKp;
                const float* r1 = as_ + (m + 8) * BKp;
                arf[tm][0] = r0[kb + tq];
                arf[tm][1] = r1[kb + tq];
                arf[tm][2] = r0[kb + tq + 4];
                arf[tm][3] = r1[kb + tq + 4];
            }
            unsigned int bfh[8][2];
            #pragma unroll
            for (int tn = 0; tn < 8; tn++) {
                int n = wn * 64 + tn * 8 + g;
                bfh[tn][0] = __float_as_uint(bs_[(kb + tq) * BNp + n]);
                bfh[tn][1] = __float_as_uint(bs_[(kb + tq + 4) * BNp + n]);
            }
            unsigned int afh[2][4], afl[2][4];
            #pragma unroll
            for (int tm = 0; tm < 2; tm++)
                #pragma unroll
                for (int q = 0; q < 4; q++) {
                    float h = tf32_rna(arf[tm][q]);
                    float l = tf32_rna(arf[tm][q] - h);
                    afh[tm][q] = __float_as_uint(h);
                    afl[tm][q] = __float_as_uint(l);
                }
            #pragma unroll
            for (int tm = 0; tm < 2; tm++)
                #pragma unroll
                for (int tn = 0; tn < 8; tn++) {
                    mma_tf32(c[tm][tn], afh[tm], bfh[tn]);
                    mma_tf32(c[tm][tn], afl[tm], bfh[tn]);
                }
        }
    }

    // ---- epilogue: fp32 attention dots + fp16 C stores ----
    const int hh = (col0 + wn * 64) / Chead;
    #pragma unroll
    for (int tm = 0; tm < 2; tm++) {
        float l0s = 0.f, l0d = 0.f, l1s = 0.f, l1d = 0.f;
        #pragma unroll
        for (int tn = 0; tn < 8; tn++) {
            int gm0 = row0 + wm * 32 + tm * 16 + g;
            int gn0 = col0 + wn * 64 + tn * 8 + 2 * tq;
            float as0 = asrc[gn0], ad0 = adst[gn0];
            float as1 = asrc[gn0 + 1], ad1 = adst[gn0 + 1];

            l0s = fmaf(c[tm][tn][0], as0, fmaf(c[tm][tn][1], as1, l0s));
            l0d = fmaf(c[tm][tn][0], ad0, fmaf(c[tm][tn][1], ad1, l0d));
            l1s = fmaf(c[tm][tn][2], as0, fmaf(c[tm][tn][3], as1, l1s));
            l1d = fmaf(c[tm][tn][2], ad0, fmaf(c[tm][tn][3], ad1, l1d));

            if (gm0 < M)
                *(__half2*)&C[(size_t)gm0 * N + gn0] =
                    __floats2half2_rn(c[tm][tn][0], c[tm][tn][1]);
            if (gm0 + 8 < M)
                *(__half2*)&C[(size_t)(gm0 + 8) * N + gn0] =
                    __floats2half2_rn(c[tm][tn][2], c[tm][tn][3]);
        }
        #pragma unroll
        for (int o = 1; o <= 2; o <<= 1) {
            l0s += __shfl_xor_sync(0xffffffffu, l0s, o);
            l0d += __shfl_xor_sync(0xffffffffu, l0d, o);
            l1s += __shfl_xor_sync(0xffffffffu, l1s, o);
            l1d += __shfl_xor_sync(0xffffffffu, l1d, o);
        }
        if (tq == 0) {
            int r0 = row0 + wm * 32 + tm * 16 + g;
            if (r0 < M) {
                atomicAdd(&als[r0 * H + hh], l0s);
                atomicAdd(&ald[r0 * H + hh], l0d);
            }
            if (r0 + 8 < M) {
                atomicAdd(&als[(r0 + 8) * H + hh], l1s);
                atomicAdd(&ald[(r0 + 8) * H + hh], l1d);
            }
        }
    }
}

// ============================================================================
// FUSED softmax + aggregation: one block (128 thr) per destination node.
// ============================================================================
__device__ __forceinline__ void acc4_h(float4& acc, float a, uint2 raw) {
    __half2 p01 = *(__half2*)&raw.x;
    __half2 p23 = *(__half2*)&raw.y;
    float2 f01 = __half22float2(p01);
    float2 f23 = __half22float2(p23);
    acc.x = fmaf(a, f01.x, acc.x); acc.y = fmaf(a, f01.y, acc.y);
    acc.z = fmaf(a, f23.x, acc.z); acc.w = fmaf(a, f23.y, acc.w);
}

template <int H, int C, int CAP, int VEC, bool ELU>
__global__ void k_fused_agg(const __half* __restrict__ h,
                            const float* __restrict__ als,
                            const float* __restrict__ ald,
                            const float* __restrict__ bias,
                            float* __restrict__ outp, int Dout)
{
    constexpr int DS = H * C;
    constexpr int BT = 128;
    __shared__ int   ssrc[CAP];
    __shared__ float salpha[CAP * H];
    __shared__ float red[BT];
    __shared__ float sals[H], sald[H], s_m[H], sexs[H], srz[H];

    const int t   = blockIdx.x;
    const int tid = threadIdx.x;
    const int beg = g_off[t], end = g_off[t + 1];
    const int deg = end - beg;
    const bool cached = (deg <= CAP);

    if (tid < H) {
        sals[tid] = als[t * H + tid];
        sald[tid] = ald[t * H + tid];
    }
    __syncthreads();

    const int hh_t = (H == 8) ? (tid & 7) : 0;
    const float myald = sald[hh_t];
    float ma = sals[hh_t];

    for (int base = 0; base < deg; base += CAP) {
        int n = min(CAP, deg - base);
        for (int i = tid; i < n; i += BT) ssrc[i] = g_csr_src[beg + base + i];
        __syncthreads();
        if (H == 8) {
            for (int j = tid; j < n * 8; j += BT) {
                float v = als[ssrc[j >> 3] * 8 + (j & 7)];
                salpha[j] = v;
                ma = fmaxf(ma, v);
            }
        } else {
            for (int i = tid; i < n; i += BT) {
                float v = als[ssrc[i]];
                salpha[i] = v;
                ma = fmaxf(ma, v);
            }
        }
        __syncthreads();
    }

    if (H == 8) {
        red[(tid & 7) * 16 + (tid >> 3)] = ma;
        __syncthreads();
        if (tid < 8) {
            float m = red[tid * 16];
            #pragma unroll
            for (int i = 1; i < 16; i++) m = fmaxf(m, red[tid * 16 + i]);
            m = lrelu(m + sald[tid]);
            s_m[tid]  = m;
            sexs[tid] = expf(lrelu(sals[tid] + sald[tid]) - m);
        }
    } else {
        #pragma unroll
        for (int o = 16; o > 0; o >>= 1)
            ma = fmaxf(ma, __shfl_xor_sync(0xffffffffu, ma, o));
        if ((tid & 31) == 0) red[tid >> 5] = ma;
        __syncthreads();
        if (tid == 0) {
            float m = fmaxf(fmaxf(red[0], red[1]), fmaxf(red[2], red[3]));
            m = lrelu(m + sald[0]);
            s_m[0]  = m;
            sexs[0] = expf(lrelu(sals[0] + sald[0]) - m);
        }
    }
    __syncthreads();
    const float mym = s_m[hh_t];

    float4 acc = make_float4(0.f, 0.f, 0.f, 0.f);
    float  acc1 = 0.f;
    int c4 = 0, hh_ch = 0;
    if (VEC == 4) {
        c4 = tid * 4;
        hh_ch = c4 / C;
        acc4_h(acc, sexs[hh_ch], *(const uint2*)&h[(size_t)t * DS + c4]);
    } else {
        acc1 = sexs[0] * __half2float(h[(size_t)t * DS + tid]);
    }

    float zloc = 0.f;
    for (int base = 0; base < deg; base += CAP) {
        int n = min(CAP, deg - base);
        if (!cached) {
            for (int i = tid; i < n; i += BT) ssrc[i] = g_csr_src[beg + base + i];
            __syncthreads();
            if (H == 8) {
                for (int j = tid; j < n * 8; j += BT) {
                    float v = als[ssrc[j >> 3] * 8 + (j & 7)];
                    float a = expf(lrelu(v + myald) - mym);
                    salpha[j] = a;
                    zloc += a;
                }
            } else {
                for (int i = tid; i < n; i += BT) {
                    float a = expf(lrelu(als[ssrc[i]] + myald) - mym);
                    salpha[i] = a;
                    zloc += a;
                }
            }
        } else {
            if (H == 8) {
                for (int j = tid; j < n * 8; j += BT) {
                    float a = expf(lrelu(salpha[j] + myald) - mym);
                    salpha[j] = a;
                    zloc += a;
                }
            } else {
                for (int i = tid; i < n; i += BT) {
                    float a = expf(lrelu(salpha[i] + myald) - mym);
                    salpha[i] = a;
                    zloc += a;
                }
            }
        }
        __syncthreads();

        if (VEC == 4) {
            int p = 0;
            for (; p + 3 < n; p += 4) {
                int s0 = ssrc[p],     s1 = ssrc[p + 1];
                int s2 = ssrc[p + 2], s3 = ssrc[p + 3];
                float a0 = salpha[(H == 8) ? (p * 8 + hh_ch)       : p];
                float a1 = salpha[(H == 8) ? ((p + 1) * 8 + hh_ch) : (p + 1)];
                float a2 = salpha[(H == 8) ? ((p + 2) * 8 + hh_ch) : (p + 2)];
                float a3 = salpha[(H == 8) ? ((p + 3) * 8 + hh_ch) : (p + 3)];
                uint2 r0 = *(const uint2*)&h[(size_t)s0 * DS + c4];
                uint2 r1 = *(const uint2*)&h[(size_t)s1 * DS + c4];
                uint2 r2 = *(const uint2*)&h[(size_t)s2 * DS + c4];
                uint2 r3 = *(const uint2*)&h[(size_t)s3 * DS + c4];
                acc4_h(acc, a0, r0);
                acc4_h(acc, a1, r1);
                acc4_h(acc, a2, r2);
                acc4_h(acc, a3, r3);
            }
            for (; p < n; p++) {
                int s0 = ssrc[p];
                float a0 = salpha[(H == 8) ? (p * 8 + hh_ch) : p];
                acc4_h(acc, a0, *(const uint2*)&h[(size_t)s0 * DS + c4]);
            }
        } else {
            int p = 0;
            for (; p + 3 < n; p += 4) {
                int s0 = ssrc[p],     s1 = ssrc[p + 1];
                int s2 = ssrc[p + 2], s3 = ssrc[p + 3];
                float a0 = salpha[p], a1 = salpha[p + 1];
                float a2 = salpha[p + 2], a3 = salpha[p + 3];
                float v0 = __half2float(h[(size_t)s0 * DS + tid]);
                float v1 = __half2float(h[(size_t)s1 * DS + tid]);
                float v2 = __half2float(h[(size_t)s2 * DS + tid]);
                float v3 = __half2float(h[(size_t)s3 * DS + tid]);
                acc1 = fmaf(a0, v0, acc1);
                acc1 = fmaf(a1, v1, acc1);
                acc1 = fmaf(a2, v2, acc1);
                acc1 = fmaf(a3, v3, acc1);
            }
            for (; p < n; p++)
                acc1 = fmaf(salpha[p],
                            __half2float(h[(size_t)ssrc[p] * DS + tid]), acc1);
        }
        __syncthreads();
    }

    if (H == 8) {
        red[(tid & 7) * 16 + (tid >> 3)] = zloc;
        __syncthreads();
        if (tid < 8) {
            float z = 0.f;
            #pragma unroll
            for (int i = 0; i < 16; i++) z += red[tid * 16 + i];
            srz[tid] = 1.f / (z + sexs[tid] + 1e-16f);
        }
    } else {
        #pragma unroll
        for (int o = 16; o > 0; o >>= 1)
            zloc += __shfl_xor_sync(0xffffffffu, zloc, o);
        if ((tid & 31) == 0) red[tid >> 5] = zloc;
        __syncthreads();
        if (tid == 0) {
            float z = red[0] + red[1] + red[2] + red[3];
            srz[0] = 1.f / (z + sexs[0] + 1e-16f);
        }
    }
    __syncthreads();

    if (VEC == 4) {
        float rz = srz[hh_ch];
        float4 b = *(const float4*)&bias[c4];
        acc.x = fmaf(acc.x, rz, b.x);
        acc.y = fmaf(acc.y, rz, b.y);
        acc.z = fmaf(acc.z, rz, b.z);
        acc.w = fmaf(acc.w, rz, b.w);
        if (ELU) {
            acc.x = acc.x > 0.f ? acc.x : expf(acc.x) - 1.f;
            acc.y = acc.y > 0.f ? acc.y : expf(acc.y) - 1.f;
            acc.z = acc.z > 0.f ? acc.z : expf(acc.z) - 1.f;
            acc.w = acc.w > 0.f ? acc.w : expf(acc.w) - 1.f;
        }
        *(float4*)&outp[(size_t)t * Dout + c4] = acc;
    } else {
        if (tid < Dout) {
            float v = fmaf(acc1, srz[0], bias[tid]);
            if (ELU) v = v > 0.f ? v : expf(v) - 1.f;
            outp[(size_t)t * Dout + tid] = v;
        }
    }
}

// ============================================================================
// Host launch — CSR build forked onto a side stream, joined before agg1.
// ============================================================================
static inline int cdiv(int a, int b) { return (a + b - 1) / b; }

extern "C" void kernel_launch(void* const* d_in, const int* in_sizes, int n_in,
                              void* d_out, int out_size) {
    const float* x   = (const float*)d_in[0];
    const void*  ei  = d_in[1];
    const float* W1  = (const float*)d_in[2];
    const float* a1s = (const float*)d_in[3];
    const float* a1d = (const float*)d_in[4];
    const float* b1  = (const float*)d_in[5];
    const float* W2  = (const float*)d_in[6];
    const float* a2s = (const float*)d_in[7];
    const float* a2d = (const float*)d_in[8];
    const float* b2  = (const float*)d_in[9];
    const float* W3  = (const float*)d_in[10];
    const float* a3s = (const float*)d_in[11];
    const float* a3d = (const float*)d_in[12];
    const float* b3  = (const float*)d_in[13];
    float* out = (float*)d_out;

    const int Nn = in_sizes[0] / 50;   // 20000
    const int E  = in_sizes[1] / 2;    // 320000

    __half* h;
    float *feat, *xpad, *w1pad, *w2r, *w3pad, *a3sp, *a3dp, *als, *ald;
    cudaGetSymbolAddress((void**)&h,     g_hh);
    cudaGetSymbolAddress((void**)&feat,  g_feat);
    cudaGetSymbolAddress((void**)&xpad,  g_xpad);
    cudaGetSymbolAddress((void**)&w1pad, g_w1pad);
    cudaGetSymbolAddress((void**)&w2r,   g_w2r);
    cudaGetSymbolAddress((void**)&w3pad, g_w3pad);
    cudaGetSymbolAddress((void**)&a3sp,  g_a3s);
    cudaGetSymbolAddress((void**)&a3dp,  g_a3d);
    cudaGetSymbolAddress((void**)&als,   g_als);
    cudaGetSymbolAddress((void**)&ald,   g_ald);

    float* als2 = als + (size_t)Nn * 8;
    float* ald2 = ald + (size_t)Nn * 8;
    float* als3 = als + (size_t)Nn * 9;
    float* ald3 = ald + (size_t)Nn * 9;

    cudaFuncSetAttribute(k_gemm_tf32,
                         cudaFuncAttributeMaxDynamicSharedMemorySize, GSMEM_BYTES);

    // ---- fork CSR build onto side stream (event fork/join; capture-legal) ----
    cudaStream_t s2;
    cudaEvent_t evF, evJ;
    cudaStreamCreateWithFlags(&s2, cudaStreamNonBlocking);
    cudaEventCreateWithFlags(&evF, cudaEventDisableTiming);
    cudaEventCreateWithFlags(&evJ, cudaEventDisableTiming);

    cudaEventRecord(evF, 0);
    cudaStreamWaitEvent(s2, evF, 0);
    k_zero_deg    <<<cdiv(Nn, 256), 256, 0, s2>>>(Nn);
    k_convert_hist<<<cdiv(E, 256), 256, 0, s2>>>((const unsigned int*)ei, E);
    k_scan        <<<1, 1024, 0, s2>>>(Nn, E);
    k_scatter     <<<cdiv(E, 256), 256, 0, s2>>>(E);
    cudaEventRecord(evJ, s2);

    // ---- main stream: setup + layer-1 GEMM (independent of CSR) ----
    k_setup<<<cdiv(Nn * K1P, 256), 256>>>(x, W1, W2, W3, a3s, a3d, Nn);

    // ---------------- Layer 1: 50 -> 8 heads x 64, concat ----------------
    {
        dim3 grid(cdiv(512, GBN), cdiv(Nn, GBM));
        k_gemm_tf32<<<grid, 256, GSMEM_BYTES>>>(xpad, w1pad, h, Nn, 512, K1P,
                                                a1s, a1d, als, ald, 8, 64);
        cudaStreamWaitEvent(0, evJ, 0);   // join: agg needs CSR
        k_fused_agg<8, 64, 256, 4, true><<<Nn, 128>>>(h, als, ald, b1, feat, 512);
    }

    // ---------------- Layer 2: 512 -> 512, 1 head ----------------
    {
        dim3 grid(cdiv(512, GBN), cdiv(Nn, GBM));
        k_gemm_tf32<<<grid, 256, GSMEM_BYTES>>>(feat, w2r, h, Nn, 512, 512,
                                                a2s, a2d, als2, ald2, 1, 512);
        k_fused_agg<1, 512, 1024, 4, true><<<Nn, 128>>>(h, als2, ald2, b2, feat, 512);
    }

    // ---------------- Layer 3: 512 -> 121 (padded to 128), mean=identity --
    {
        dim3 grid(cdiv(N3P, GBN), cdiv(Nn, GBM));
        k_gemm_tf32<<<grid, 256, GSMEM_BYTES>>>(feat, w3pad, h, Nn, N3P, 512,
                                                a3sp, a3dp, als3, ald3, 1, N3P);
        k_fused_agg<1, 128, 1024, 1, false><<<Nn, 128>>>(h, als3, ald3, b3, out, 121);
    }
}

// round 17
// speedup vs baseline: 1.3008x; 1.2190x over previous
#include <cuda_runtime.h>
#include <cuda_fp16.h>
#include <math.h>
#include <stdint.h>

// ============================================================================
// Problem constants
// ============================================================================
#define NMAX   20000
#define EMAX   320000
#define DMAX   512
#define HMAX   8
#define K1P    52      // layer-1 K padded (50 -> 52)
#define N3P    128     // layer-3 N padded (121 -> 128)

// ============================================================================
// Scratch (static device globals)
// ============================================================================
__device__ int    g_src[EMAX];
__device__ int    g_dst[EMAX];
__device__ int    g_deg[NMAX];
__device__ int    g_off[NMAX + 1];
__device__ int    g_cur[NMAX];
__device__ int    g_csr_src[EMAX];
__device__ __half g_hh   [(size_t)NMAX * DMAX];  // fp16 features (agg input)
__device__ __half g_feath[(size_t)NMAX * DMAX];  // fp16 layer activations
__device__ float  g_als [NMAX * 10];   // L1 [0,8N), L2 [8N,9N), L3 [9N,10N)
__device__ float  g_ald [NMAX * 10];
__device__ float  g_xpad [(size_t)NMAX * K1P];
__device__ float  g_w1pad[K1P * 512];            // tf32-rounded
__device__ float  g_w2r  [512 * 512];            // tf32-rounded W2
__device__ float  g_w3pad[512 * N3P];            // tf32-rounded
__device__ float  g_a3s  [N3P];
__device__ float  g_a3d  [N3P];

// ============================================================================
// Helpers
// ============================================================================
__device__ __forceinline__ float lrelu(float x) { return x > 0.f ? x : 0.2f * x; }

__device__ __forceinline__ float tf32_rna(float x) {
    unsigned int r;
    asm("cvt.rna.tf32.f32 %0, %1;" : "=r"(r) : "f"(x));
    return __uint_as_float(r);
}

__device__ __forceinline__ uint32_t smem_u32(const void* p) {
    uint32_t a;
    asm("{ .reg .u64 t; cvta.to.shared.u64 t, %1; cvt.u32.u64 %0, t; }"
        : "=r"(a) : "l"(p));
    return a;
}

// ============================================================================
// Setup: dot-buffer zero + padding + tf32 pre-rounding of B (legacy stream)
// ============================================================================
__global__ void k_setup(const float* __restrict__ x,
                        const float* __restrict__ W1,
                        const float* __restrict__ W2,
                        const float* __restrict__ W3,
                        const float* __restrict__ a3s,
                        const float* __restrict__ a3d, int Nn) {
    int i = blockIdx.x * blockDim.x + threadIdx.x;
    if (i < Nn * 10) { g_als[i] = 0.f; g_ald[i] = 0.f; }
    if (i < Nn * K1P) {
        int r = i / K1P, c = i - r * K1P;
        g_xpad[i] = (c < 50) ? x[r * 50 + c] : 0.f;
    }
    if (i < K1P * 512) {
        int k = i >> 9;
        g_w1pad[i] = (k < 50) ? tf32_rna(W1[i]) : 0.f;
    }
    if (i < 512 * 512)
        g_w2r[i] = tf32_rna(W2[i]);
    if (i < 512 * N3P) {
        int k = i >> 7, n = i & 127;
        g_w3pad[i] = (n < 121) ? tf32_rna(W3[k * 121 + n]) : 0.f;
    }
    if (i < N3P) {
        g_a3s[i] = (i < 121) ? a3s[i] : 0.f;
        g_a3d[i] = (i < 121) ? a3d[i] : 0.f;
    }
}

// ---- CSR chain (side stream) ----
__global__ void k_zero_deg(int Nn) {
    int i = blockIdx.x * blockDim.x + threadIdx.x;
    if (i < Nn) g_deg[i] = 0;
}

__global__ void k_convert_hist(const unsigned int* __restrict__ w, int E) {
    bool is64 = true;
    #pragma unroll
    for (int i = 1; i < 64; i += 2) {
        if (w[i] != 0u) { is64 = false; break; }
    }
    int e = blockIdx.x * blockDim.x + threadIdx.x;
    if (e < E) {
        int s, d;
        if (is64) { s = (int)w[2 * e]; d = (int)w[2 * (E + e)]; }
        else      { s = (int)w[e];     d = (int)w[E + e]; }
        g_src[e] = s;
        g_dst[e] = d;
        atomicAdd(&g_deg[d], 1);
    }
}

__global__ void k_scan(int Nn, int E) {
    __shared__ int wsum[32];
    const int T = 1024;
    const int tid  = threadIdx.x;
    const int lane = tid & 31, w = tid >> 5;
    const int CH = (Nn + T - 1) / T;
    int base = tid * CH;
    int lim  = Nn - base;
    if (lim < 0) lim = 0;
    if (lim > CH) lim = CH;

    int sum = 0;
    for (int j = 0; j < lim; j++) sum += g_deg[base + j];

    int v = sum;
    #pragma unroll
    for (int o = 1; o < 32; o <<= 1) {
        int t = __shfl_up_sync(0xffffffffu, v, o);
        if (lane >= o) v += t;
    }
    if (lane == 31) wsum[w] = v;
    __syncthreads();
    if (w == 0) {
        int s = wsum[lane];
        #pragma unroll
        for (int o = 1; o < 32; o <<= 1) {
            int t = __shfl_up_sync(0xffffffffu, s, o);
            if (lane >= o) s += t;
        }
        wsum[lane] = s;
    }
    __syncthreads();
    int run = v - sum + (w > 0 ? wsum[w - 1] : 0);
    for (int j = 0; j < lim; j++) {
        g_off[base + j] = run;
        g_cur[base + j] = run;
        run += g_deg[base + j];
    }
    if (tid == 0) g_off[Nn] = E;
}

__global__ void k_scatter(int E) {
    int e = blockIdx.x * blockDim.x + threadIdx.x;
    if (e < E) {
        int p = atomicAdd(&g_cur[g_dst[e]], 1);
        g_csr_src[p] = g_src[e];
    }
}

// ============================================================================
// GEMM common: 128x128 block tile, BK=16, 8 warps (warp tile 32x64).
// B pre-rounded tf32 fp32. cp.async 3-stage pipeline. fp16 C stores;
// fp32 attention dots fused in epilogue.
// ============================================================================
#define GBM 128
#define GBN 128
#define GBK 16
#define BKp 20           // fp32 A row stride (floats)
#define BKh 24           // fp16 A row stride (halfs) -> 48 B, 16B aligned
#define BNp 132
#define ABUF  (GBM * BKp * 4)           // fp32 A tile
#define ABUFH (GBM * BKh * 2)           // fp16 A tile = 6144
#define BBUF  (GBK * BNp * 4)
#define BUFB  (ABUF + BBUF)
#define BUFBH (ABUFH + BBUF)
#define GSMEM_BYTES  (3 * BUFB)
#define GSMEM_BYTESH (3 * BUFBH)

__device__ __forceinline__ void mma_tf32(float c[4], const unsigned int a[4],
                                         const unsigned int b[2]) {
    asm volatile(
        "mma.sync.aligned.m16n8k8.row.col.f32.tf32.tf32.f32 "
        "{%0,%1,%2,%3}, {%4,%5,%6,%7}, {%8,%9}, {%0,%1,%2,%3};\n"
        : "+f"(c[0]), "+f"(c[1]), "+f"(c[2]), "+f"(c[3])
        : "r"(a[0]), "r"(a[1]), "r"(a[2]), "r"(a[3]), "r"(b[0]), "r"(b[1]));
}

__device__ __forceinline__ void cp_issue_B(
    const float* __restrict__ B, int Ncols, int K, int col0, int k0,
    int tid, uint32_t smbufB)
{
    const int bk = tid >> 4, bn = (tid & 15) * 8;
    const int gk = k0 + bk, gn = col0 + bn;
    const bool kok = gk < K;
    const float* bp = B + (size_t)(kok ? gk : 0) * Ncols + gn;
    const uint32_t bd = smbufB + (bk * BNp + bn) * 4;
    int szb0 = (kok && gn < Ncols) ? 16 : 0;
    int szb1 = (kok && gn + 4 < Ncols) ? 16 : 0;
    asm volatile("cp.async.cg.shared.global [%0], [%1], 16, %2;"
                 :: "r"(bd), "l"(bp), "r"(szb0));
    asm volatile("cp.async.cg.shared.global [%0], [%1], 16, %2;"
                 :: "r"(bd + 16), "l"(bp + 4), "r"(szb1));
}

// ---------------- fp32-A, 2-term (layer 1) ----------------
__device__ __forceinline__ void cp_issue_tile_f32(
    const float* __restrict__ A, const float* __restrict__ B,
    int M, int Ncols, int K, int row0, int col0, int k0,
    int tid, uint32_t smbuf)
{
    const int arow = tid >> 1, akb = (tid & 1) * 8;
    const int grow = row0 + arow;
    const bool rok = grow < M;
    const float* ap = A + (size_t)(rok ? grow : 0) * K + k0 + akb;
    const uint32_t ad = smbuf + (arow * BKp + akb) * 4;
    int sza0 = (rok && k0 + akb < K) ? 16 : 0;
    int sza1 = (rok && k0 + akb + 4 < K) ? 16 : 0;
    asm volatile("cp.async.cg.shared.global [%0], [%1], 16, %2;"
                 :: "r"(ad), "l"(ap), "r"(sza0));
    asm volatile("cp.async.cg.shared.global [%0], [%1], 16, %2;"
                 :: "r"(ad + 16), "l"(ap + 4), "r"(sza1));
    cp_issue_B(B, Ncols, K, col0, k0, tid, smbuf + ABUF);
}

// ---------------- fp16-A, 1-term (layers 2/3) ----------------
__device__ __forceinline__ void cp_issue_tile_f16(
    const __half* __restrict__ A, const float* __restrict__ B,
    int M, int Ncols, int K, int row0, int col0, int k0,
    int tid, uint32_t smbuf)
{
    const int arow = tid >> 1, akb = (tid & 1) * 8;
    const int grow = row0 + arow;
    const bool rok = grow < M;
    const __half* ap = A + (size_t)(rok ? grow : 0) * K + k0 + akb;
    const uint32_t ad = smbuf + (arow * BKh + akb) * 2;
    int sz = (rok && k0 + akb < K) ? 16 : 0;   // 8 halfs = 16 B
    asm volatile("cp.async.cg.shared.global [%0], [%1], 16, %2;"
                 :: "r"(ad), "l"(ap), "r"(sz));
    cp_issue_B(B, Ncols, K, col0, k0, tid, smbuf + ABUFH);
}

// shared epilogue
__device__ __forceinline__ void gemm_epilogue(
    float c[2][8][4], __half* __restrict__ C, int M, int N,
    const float* __restrict__ asrc, const float* __restrict__ adst,
    float* __restrict__ als, float* __restrict__ ald,
    int H, int Chead, int row0, int col0, int wm, int wn, int g, int tq)
{
    const int hh = (col0 + wn * 64) / Chead;
    #pragma unroll
    for (int tm = 0; tm < 2; tm++) {
        float l0s = 0.f, l0d = 0.f, l1s = 0.f, l1d = 0.f;
        #pragma unroll
        for (int tn = 0; tn < 8; tn++) {
            int gm0 = row0 + wm * 32 + tm * 16 + g;
            int gn0 = col0 + wn * 64 + tn * 8 + 2 * tq;
            float as0 = asrc[gn0], ad0 = adst[gn0];
            float as1 = asrc[gn0 + 1], ad1 = adst[gn0 + 1];

            l0s = fmaf(c[tm][tn][0], as0, fmaf(c[tm][tn][1], as1, l0s));
            l0d = fmaf(c[tm][tn][0], ad0, fmaf(c[tm][tn][1], ad1, l0d));
            l1s = fmaf(c[tm][tn][2], as0, fmaf(c[tm][tn][3], as1, l1s));
            l1d = fmaf(c[tm][tn][2], ad0, fmaf(c[tm][tn][3], ad1, l1d));

            if (gm0 < M)
                *(__half2*)&C[(size_t)gm0 * N + gn0] =
                    __floats2half2_rn(c[tm][tn][0], c[tm][tn][1]);
            if (gm0 + 8 < M)
                *(__half2*)&C[(size_t)(gm0 + 8) * N + gn0] =
                    __floats2half2_rn(c[tm][tn][2], c[tm][tn][3]);
        }
        #pragma unroll
        for (int o = 1; o <= 2; o <<= 1) {
            l0s += __shfl_xor_sync(0xffffffffu, l0s, o);
            l0d += __shfl_xor_sync(0xffffffffu, l0d, o);
            l1s += __shfl_xor_sync(0xffffffffu, l1s, o);
            l1d += __shfl_xor_sync(0xffffffffu, l1d, o);
        }
        if (tq == 0) {
            int r0 = row0 + wm * 32 + tm * 16 + g;
            if (r0 < M) {
                atomicAdd(&als[r0 * H + hh], l0s);
                atomicAdd(&ald[r0 * H + hh], l0d);
            }
            if (r0 + 8 < M) {
                atomicAdd(&als[(r0 + 8) * H + hh], l1s);
                atomicAdd(&ald[(r0 + 8) * H + hh], l1d);
            }
        }
    }
}

__global__ __launch_bounds__(256, 2) void k_gemm_tf32(
    const float* __restrict__ A, const float* __restrict__ B,
    __half* __restrict__ C, int M, int N, int K,
    const float* __restrict__ asrc, const float* __restrict__ adst,
    float* __restrict__ als, float* __restrict__ ald,
    int H, int Chead)
{
    extern __shared__ char sm[];
    const uint32_t smb = smem_u32(sm);

    const int tid  = threadIdx.x;
    const int lane = tid & 31, warp = tid >> 5;
    const int wm = warp >> 1, wn = warp & 1;
    const int g = lane >> 2, tq = lane & 3;
    const int row0 = blockIdx.y * GBM;
    const int col0 = blockIdx.x * GBN;

    float c[2][8][4];
    #pragma unroll
    for (int i = 0; i < 2; i++)
        #pragma unroll
        for (int j = 0; j < 8; j++)
            #pragma unroll
            for (int q = 0; q < 4; q++) c[i][j][q] = 0.f;

    const int nIt = (K + GBK - 1) / GBK;

    cp_issue_tile_f32(A, B, M, N, K, row0, col0, 0, tid, smb);
    asm volatile("cp.async.commit_group;" ::: "memory");
    if (nIt > 1) {
        cp_issue_tile_f32(A, B, M, N, K, row0, col0, GBK, tid, smb + BUFB);
        asm volatile("cp.async.commit_group;" ::: "memory");
    }

    for (int it = 0; it < nIt; it++) {
        if (it < nIt - 1)
            asm volatile("cp.async.wait_group 1;" ::: "memory");
        else
            asm volatile("cp.async.wait_group 0;" ::: "memory");
        __syncthreads();

        if (it + 2 < nIt) {
            cp_issue_tile_f32(A, B, M, N, K, row0, col0, (it + 2) * GBK, tid,
                              smb + ((it + 2) % 3) * BUFB);
            asm volatile("cp.async.commit_group;" ::: "memory");
        }

        const float* as_ = (const float*)(sm + (it % 3) * BUFB);
        const float* bs_ = (const float*)(sm + (it % 3) * BUFB + ABUF);

        #pragma unroll
        for (int ks = 0; ks < 2; ks++) {
            const int kb = ks * 8;
            float arf[2][4];
            #pragma unroll
            for (int tm = 0; tm < 2; tm++) {
                int m = wm * 32 + tm * 16 + g;
                const float* r0 = as_ + m * BKp;
                const float* r1 = as_ + (m + 8) * BKp;
                arf[tm][0] = r0[kb + tq];
                arf[tm][1] = r1[kb + tq];
                arf[tm][2] = r0[kb + tq + 4];
                arf[tm][3] = r1[kb + tq + 4];
            }
            unsigned int bfh[8][2];
            #pragma unroll
            for (int tn = 0; tn < 8; tn++) {
                int n = wn * 64 + tn * 8 + g;
                bfh[tn][0] = __float_as_uint(bs_[(kb + tq) * BNp + n]);
                bfh[tn][1] = __float_as_uint(bs_[(kb + tq + 4) * BNp + n]);
            }
            unsigned int afh[2][4], afl[2][4];
            #pragma unroll
            for (int tm = 0; tm < 2; tm++)
                #pragma unroll
                for (int q = 0; q < 4; q++) {
                    float h = tf32_rna(arf[tm][q]);
                    float l = tf32_rna(arf[tm][q] - h);
                    afh[tm][q] = __float_as_uint(h);
                    afl[tm][q] = __float_as_uint(l);
                }
            #pragma unroll
            for (int tm = 0; tm < 2; tm++)
                #pragma unroll
                for (int tn = 0; tn < 8; tn++) {
                    mma_tf32(c[tm][tn], afh[tm], bfh[tn]);
                    mma_tf32(c[tm][tn], afl[tm], bfh[tn]);
                }
        }
    }
    gemm_epilogue(c, C, M, N, asrc, adst, als, ald, H, Chead,
                  row0, col0, wm, wn, g, tq);
}

__global__ __launch_bounds__(256, 2) void k_gemm_f16a(
    const __half* __restrict__ A, const float* __restrict__ B,
    __half* __restrict__ C, int M, int N, int K,
    const float* __restrict__ asrc, const float* __restrict__ adst,
    float* __restrict__ als, float* __restrict__ ald,
    int H, int Chead)
{
    extern __shared__ char sm[];
    const uint32_t smb = smem_u32(sm);

    const int tid  = threadIdx.x;
    const int lane = tid & 31, warp = tid >> 5;
    const int wm = warp >> 1, wn = warp & 1;
    const int g = lane >> 2, tq = lane & 3;
    const int row0 = blockIdx.y * GBM;
    const int col0 = blockIdx.x * GBN;

    float c[2][8][4];
    #pragma unroll
    for (int i = 0; i < 2; i++)
        #pragma unroll
        for (int j = 0; j < 8; j++)
            #pragma unroll
            for (int q = 0; q < 4; q++) c[i][j][q] = 0.f;

    const int nIt = (K + GBK - 1) / GBK;

    cp_issue_tile_f16(A, B, M, N, K, row0, col0, 0, tid, smb);
    asm volatile("cp.async.commit_group;" ::: "memory");
    if (nIt > 1) {
        cp_issue_tile_f16(A, B, M, N, K, row0, col0, GBK, tid, smb + BUFBH);
        asm volatile("cp.async.commit_group;" ::: "memory");
    }

    for (int it = 0; it < nIt; it++) {
        if (it < nIt - 1)
            asm volatile("cp.async.wait_group 1;" ::: "memory");
        else
            asm volatile("cp.async.wait_group 0;" ::: "memory");
        __syncthreads();

        if (it + 2 < nIt) {
            cp_issue_tile_f16(A, B, M, N, K, row0, col0, (it + 2) * GBK, tid,
                              smb + ((it + 2) % 3) * BUFBH);
            asm volatile("cp.async.commit_group;" ::: "memory");
        }

        const __half* as_ = (const __half*)(sm + (it % 3) * BUFBH);
        const float*  bs_ = (const float*)(sm + (it % 3) * BUFBH + ABUFH);

        #pragma unroll
        for (int ks = 0; ks < 2; ks++) {
            const int kb = ks * 8;
            unsigned int afh[2][4];
            #pragma unroll
            for (int tm = 0; tm < 2; tm++) {
                int m = wm * 32 + tm * 16 + g;
                const __half* r0 = as_ + m * BKh;
                const __half* r1 = as_ + (m + 8) * BKh;
                // fp16 -> fp32 is exact; result is already tf32-valid
                afh[tm][0] = __float_as_uint(__half2float(r0[kb + tq]));
                afh[tm][1] = __float_as_uint(__half2float(r1[kb + tq]));
                afh[tm][2] = __float_as_uint(__half2float(r0[kb + tq + 4]));
                afh[tm][3] = __float_as_uint(__half2float(r1[kb + tq + 4]));
            }
            unsigned int bfh[8][2];
            #pragma unroll
            for (int tn = 0; tn < 8; tn++) {
                int n = wn * 64 + tn * 8 + g;
                bfh[tn][0] = __float_as_uint(bs_[(kb + tq) * BNp + n]);
                bfh[tn][1] = __float_as_uint(bs_[(kb + tq + 4) * BNp + n]);
            }
            #pragma unroll
            for (int tm = 0; tm < 2; tm++)
                #pragma unroll
                for (int tn = 0; tn < 8; tn++)
                    mma_tf32(c[tm][tn], afh[tm], bfh[tn]);
        }
    }
    gemm_epilogue(c, C, M, N, asrc, adst, als, ald, H, Chead,
                  row0, col0, wm, wn, g, tq);
}

// ============================================================================
// FUSED softmax + aggregation: one block (128 thr) per destination node.
// OutT = __half (feat layers) or float (final output).
// ============================================================================
__device__ __forceinline__ void acc4_h(float4& acc, float a, uint2 raw) {
    __half2 p01 = *(__half2*)&raw.x;
    __half2 p23 = *(__half2*)&raw.y;
    float2 f01 = __half22float2(p01);
    float2 f23 = __half22float2(p23);
    acc.x = fmaf(a, f01.x, acc.x); acc.y = fmaf(a, f01.y, acc.y);
    acc.z = fmaf(a, f23.x, acc.z); acc.w = fmaf(a, f23.y, acc.w);
}

__device__ __forceinline__ void store_out4(float* p, float4 v) {
    *(float4*)p = v;
}
__device__ __forceinline__ void store_out4(__half* p, float4 v) {
    __half2 h01 = __floats2half2_rn(v.x, v.y);
    __half2 h23 = __floats2half2_rn(v.z, v.w);
    uint2 raw;
    raw.x = *(unsigned int*)&h01;
    raw.y = *(unsigned int*)&h23;
    *(uint2*)p = raw;
}

template <int H, int C, int CAP, int VEC, bool ELU, typename OutT>
__global__ void k_fused_agg(const __half* __restrict__ h,
                            const float* __restrict__ als,
                            const float* __restrict__ ald,
                            const float* __restrict__ bias,
                            OutT* __restrict__ outp, int Dout)
{
    constexpr int DS = H * C;
    constexpr int BT = 128;
    __shared__ int   ssrc[CAP];
    __shared__ float salpha[CAP * H];
    __shared__ float red[BT];
    __shared__ float sals[H], sald[H], s_m[H], sexs[H], srz[H];

    const int t   = blockIdx.x;
    const int tid = threadIdx.x;
    const int beg = g_off[t], end = g_off[t + 1];
    const int deg = end - beg;
    const bool cached = (deg <= CAP);

    if (tid < H) {
        sals[tid] = als[t * H + tid];
        sald[tid] = ald[t * H + tid];
    }
    __syncthreads();

    const int hh_t = (H == 8) ? (tid & 7) : 0;
    const float myald = sald[hh_t];
    float ma = sals[hh_t];

    for (int base = 0; base < deg; base += CAP) {
        int n = min(CAP, deg - base);
        for (int i = tid; i < n; i += BT) ssrc[i] = g_csr_src[beg + base + i];
        __syncthreads();
        if (H == 8) {
            for (int j = tid; j < n * 8; j += BT) {
                float v = als[ssrc[j >> 3] * 8 + (j & 7)];
                salpha[j] = v;
                ma = fmaxf(ma, v);
            }
        } else {
            for (int i = tid; i < n; i += BT) {
                float v = als[ssrc[i]];
                salpha[i] = v;
                ma = fmaxf(ma, v);
            }
        }
        __syncthreads();
    }

    if (H == 8) {
        red[(tid & 7) * 16 + (tid >> 3)] = ma;
        __syncthreads();
        if (tid < 8) {
            float m = red[tid * 16];
            #pragma unroll
            for (int i = 1; i < 16; i++) m = fmaxf(m, red[tid * 16 + i]);
            m = lrelu(m + sald[tid]);
            s_m[tid]  = m;
            sexs[tid] = expf(lrelu(sals[tid] + sald[tid]) - m);
        }
    } else {
        #pragma unroll
        for (int o = 16; o > 0; o >>= 1)
            ma = fmaxf(ma, __shfl_xor_sync(0xffffffffu, ma, o));
        if ((tid & 31) == 0) red[tid >> 5] = ma;
        __syncthreads();
        if (tid == 0) {
            float m = fmaxf(fmaxf(red[0], red[1]), fmaxf(red[2], red[3]));
            m = lrelu(m + sald[0]);
            s_m[0]  = m;
            sexs[0] = expf(lrelu(sals[0] + sald[0]) - m);
        }
    }
    __syncthreads();
    const float mym = s_m[hh_t];

    float4 acc = make_float4(0.f, 0.f, 0.f, 0.f);
    float  acc1 = 0.f;
    int c4 = 0, hh_ch = 0;
    if (VEC == 4) {
        c4 = tid * 4;
        hh_ch = c4 / C;
        acc4_h(acc, sexs[hh_ch], *(const uint2*)&h[(size_t)t * DS + c4]);
    } else {
        acc1 = sexs[0] * __half2float(h[(size_t)t * DS + tid]);
    }

    float zloc = 0.f;
    for (int base = 0; base < deg; base += CAP) {
        int n = min(CAP, deg - base);
        if (!cached) {
            for (int i = tid; i < n; i += BT) ssrc[i] = g_csr_src[beg + base + i];
            __syncthreads();
            if (H == 8) {
                for (int j = tid; j < n * 8; j += BT) {
                    float v = als[ssrc[j >> 3] * 8 + (j & 7)];
                    float a = expf(lrelu(v + myald) - mym);
                    salpha[j] = a;
                    zloc += a;
                }
            } else {
                for (int i = tid; i < n; i += BT) {
                    float a = expf(lrelu(als[ssrc[i]] + myald) - mym);
                    salpha[i] = a;
                    zloc += a;
                }
            }
        } else {
            if (H == 8) {
                for (int j = tid; j < n * 8; j += BT) {
                    float a = expf(lrelu(salpha[j] + myald) - mym);
                    salpha[j] = a;
                    zloc += a;
                }
            } else {
                for (int i = tid; i < n; i += BT) {
                    float a = expf(lrelu(salpha[i] + myald) - mym);
                    salpha[i] = a;
                    zloc += a;
                }
            }
        }
        __syncthreads();

        if (VEC == 4) {
            int p = 0;
            for (; p + 3 < n; p += 4) {
                int s0 = ssrc[p],     s1 = ssrc[p + 1];
                int s2 = ssrc[p + 2], s3 = ssrc[p + 3];
                float a0 = salpha[(H == 8) ? (p * 8 + hh_ch)       : p];
                float a1 = salpha[(H == 8) ? ((p + 1) * 8 + hh_ch) : (p + 1)];
                float a2 = salpha[(H == 8) ? ((p + 2) * 8 + hh_ch) : (p + 2)];
                float a3 = salpha[(H == 8) ? ((p + 3) * 8 + hh_ch) : (p + 3)];
                uint2 r0 = *(const uint2*)&h[(size_t)s0 * DS + c4];
                uint2 r1 = *(const uint2*)&h[(size_t)s1 * DS + c4];
                uint2 r2 = *(const uint2*)&h[(size_t)s2 * DS + c4];
                uint2 r3 = *(const uint2*)&h[(size_t)s3 * DS + c4];
                acc4_h(acc, a0, r0);
                acc4_h(acc, a1, r1);
                acc4_h(acc, a2, r2);
                acc4_h(acc, a3, r3);
            }
            for (; p < n; p++) {
                int s0 = ssrc[p];
                float a0 = salpha[(H == 8) ? (p * 8 + hh_ch) : p];
                acc4_h(acc, a0, *(const uint2*)&h[(size_t)s0 * DS + c4]);
            }
        } else {
            int p = 0;
            for (; p + 3 < n; p += 4) {
                int s0 = ssrc[p],     s1 = ssrc[p + 1];
                int s2 = ssrc[p + 2], s3 = ssrc[p + 3];
                float a0 = salpha[p], a1 = salpha[p + 1];
                float a2 = salpha[p + 2], a3 = salpha[p + 3];
                float v0 = __half2float(h[(size_t)s0 * DS + tid]);
                float v1 = __half2float(h[(size_t)s1 * DS + tid]);
                float v2 = __half2float(h[(size_t)s2 * DS + tid]);
                float v3 = __half2float(h[(size_t)s3 * DS + tid]);
                acc1 = fmaf(a0, v0, acc1);
                acc1 = fmaf(a1, v1, acc1);
                acc1 = fmaf(a2, v2, acc1);
                acc1 = fmaf(a3, v3, acc1);
            }
            for (; p < n; p++)
                acc1 = fmaf(salpha[p],
                            __half2float(h[(size_t)ssrc[p] * DS + tid]), acc1);
        }
        __syncthreads();
    }

    if (H == 8) {
        red[(tid & 7) * 16 + (tid >> 3)] = zloc;
        __syncthreads();
        if (tid < 8) {
            float z = 0.f;
            #pragma unroll
            for (int i = 0; i < 16; i++) z += red[tid * 16 + i];
            srz[tid] = 1.f / (z + sexs[tid] + 1e-16f);
        }
    } else {
        #pragma unroll
        for (int o = 16; o > 0; o >>= 1)
            zloc += __shfl_xor_sync(0xffffffffu, zloc, o);
        if ((tid & 31) == 0) red[tid >> 5] = zloc;
        __syncthreads();
        if (tid == 0) {
            float z = red[0] + red[1] + red[2] + red[3];
            srz[0] = 1.f / (z + sexs[0] + 1e-16f);
        }
    }
    __syncthreads();

    if (VEC == 4) {
        float rz = srz[hh_ch];
        float4 b = *(const float4*)&bias[c4];
        acc.x = fmaf(acc.x, rz, b.x);
        acc.y = fmaf(acc.y, rz, b.y);
        acc.z = fmaf(acc.z, rz, b.z);
        acc.w = fmaf(acc.w, rz, b.w);
        if (ELU) {
            acc.x = acc.x > 0.f ? acc.x : expf(acc.x) - 1.f;
            acc.y = acc.y > 0.f ? acc.y : expf(acc.y) - 1.f;
            acc.z = acc.z > 0.f ? acc.z : expf(acc.z) - 1.f;
            acc.w = acc.w > 0.f ? acc.w : expf(acc.w) - 1.f;
        }
        store_out4(&outp[(size_t)t * Dout + c4], acc);
    } else {
        if (tid < Dout) {
            float v = fmaf(acc1, srz[0], bias[tid]);
            if (ELU) v = v > 0.f ? v : expf(v) - 1.f;
            outp[(size_t)t * Dout + tid] = (OutT)v;
        }
    }
}

// ============================================================================
// Host launch — CSR build forked onto a side stream, joined before agg1.
// ============================================================================
static inline int cdiv(int a, int b) { return (a + b - 1) / b; }

extern "C" void kernel_launch(void* const* d_in, const int* in_sizes, int n_in,
                              void* d_out, int out_size) {
    const float* x   = (const float*)d_in[0];
    const void*  ei  = d_in[1];
    const float* W1  = (const float*)d_in[2];
    const float* a1s = (const float*)d_in[3];
    const float* a1d = (const float*)d_in[4];
    const float* b1  = (const float*)d_in[5];
    const float* W2  = (const float*)d_in[6];
    const float* a2s = (const float*)d_in[7];
    const float* a2d = (const float*)d_in[8];
    const float* b2  = (const float*)d_in[9];
    const float* W3  = (const float*)d_in[10];
    const float* a3s = (const float*)d_in[11];
    const float* a3d = (const float*)d_in[12];
    const float* b3  = (const float*)d_in[13];
    float* out = (float*)d_out;

    const int Nn = in_sizes[0] / 50;   // 20000
    const int E  = in_sizes[1] / 2;    // 320000

    __half *h, *feath;
    float *xpad, *w1pad, *w2r, *w3pad, *a3sp, *a3dp, *als, *ald;
    cudaGetSymbolAddress((void**)&h,     g_hh);
    cudaGetSymbolAddress((void**)&feath, g_feath);
    cudaGetSymbolAddress((void**)&xpad,  g_xpad);
    cudaGetSymbolAddress((void**)&w1pad, g_w1pad);
    cudaGetSymbolAddress((void**)&w2r,   g_w2r);
    cudaGetSymbolAddress((void**)&w3pad, g_w3pad);
    cudaGetSymbolAddress((void**)&a3sp,  g_a3s);
    cudaGetSymbolAddress((void**)&a3dp,  g_a3d);
    cudaGetSymbolAddress((void**)&als,   g_als);
    cudaGetSymbolAddress((void**)&ald,   g_ald);

    float* als2 = als + (size_t)Nn * 8;
    float* ald2 = ald + (size_t)Nn * 8;
    float* als3 = als + (size_t)Nn * 9;
    float* ald3 = ald + (size_t)Nn * 9;

    cudaFuncSetAttribute(k_gemm_tf32,
                         cudaFuncAttributeMaxDynamicSharedMemorySize, GSMEM_BYTES);
    cudaFuncSetAttribute(k_gemm_f16a,
                         cudaFuncAttributeMaxDynamicSharedMemorySize, GSMEM_BYTESH);

    // ---- fork CSR build onto side stream (event fork/join) ----
    cudaStream_t s2;
    cudaEvent_t evF, evJ;
    cudaStreamCreateWithFlags(&s2, cudaStreamNonBlocking);
    cudaEventCreateWithFlags(&evF, cudaEventDisableTiming);
    cudaEventCreateWithFlags(&evJ, cudaEventDisableTiming);

    cudaEventRecord(evF, 0);
    cudaStreamWaitEvent(s2, evF, 0);
    k_zero_deg    <<<cdiv(Nn, 256), 256, 0, s2>>>(Nn);
    k_convert_hist<<<cdiv(E, 256), 256, 0, s2>>>((const unsigned int*)ei, E);
    k_scan        <<<1, 1024, 0, s2>>>(Nn, E);
    k_scatter     <<<cdiv(E, 256), 256, 0, s2>>>(E);
    cudaEventRecord(evJ, s2);

    // ---- main stream ----
    k_setup<<<cdiv(Nn * K1P, 256), 256>>>(x, W1, W2, W3, a3s, a3d, Nn);

    // ---------------- Layer 1: 50 -> 8 heads x 64, concat ----------------
    {
        dim3 grid(cdiv(512, GBN), cdiv(Nn, GBM));
        k_gemm_tf32<<<grid, 256, GSMEM_BYTES>>>(xpad, w1pad, h, Nn, 512, K1P,
                                                a1s, a1d, als, ald, 8, 64);
        cudaStreamWaitEvent(0, evJ, 0);
        k_fused_agg<8, 64, 256, 4, true, __half><<<Nn, 128>>>(
            h, als, ald, b1, feath, 512);
    }

    // ---------------- Layer 2: 512 -> 512, 1 head ----------------
    {
        dim3 grid(cdiv(512, GBN), cdiv(Nn, GBM));
        k_gemm_f16a<<<grid, 256, GSMEM_BYTESH>>>(feath, w2r, h, Nn, 512, 512,
                                                 a2s, a2d, als2, ald2, 1, 512);
        k_fused_agg<1, 512, 1024, 4, true, __half><<<Nn, 128>>>(
            h, als2, ald2, b2, feath, 512);
    }

    // ---------------- Layer 3: 512 -> 121 (padded to 128), mean=identity --
    {
        dim3 grid(cdiv(N3P, GBN), cdiv(Nn, GBM));
        k_gemm_f16a<<<grid, 256, GSMEM_BYTESH>>>(feath, w3pad, h, Nn, N3P, 512,
                                                 a3sp, a3dp, als3, ald3, 1, N3P);
        k_fused_agg<1, 128, 1024, 1, false, float><<<Nn, 128>>>(
            h, als3, ald3, b3, out, 121);
    }
}